// round 4
// baseline (speedup 1.0000x reference)
#include <cuda_runtime.h>
#include <cuda_bf16.h>
#include <cstdint>

// EngramMemory: rolling-hash n-gram gather.
// tokens: (4, 4096)  int32 (int64 in the JAX ref, downcast by the harness) -> d_in[tokens]
// tables: (8, 2048, 256) f32 -> d_in[tables]
// out:    (4, 4096, 2048) f32
//
// out[b][s][oi*1024 + head*256 + d] = tables[oi*4+head][h][d]
//   h = fold over the order-(2+oi) n-gram ending at s:
//       h = (h*1000003 + tok + seed) % 2048, seed = 1337 + 97*(2+oi) + 17*head
//   left zero-padded (pos < 0 -> token 0).
//
// All hash arithmetic fits in uint32: max h*PRIME + tok + seed
//   = 2047*1000003 + 50256 + 1679 ~= 2.048e9 < 2^31. '% 2048' == '& 2047'.

namespace {
constexpr int B = 4;
constexpr int S = 4096;
constexpr int NUM_BUCKETS = 2048;
constexpr int HEAD_DIM = 256;
constexpr int PARTS = 8;                   // 2 orders * 4 heads
constexpr int OUT_ROW = PARTS * HEAD_DIM;  // 2048 floats per (b,s)
constexpr unsigned PRIME = 1000003u;

__global__ __launch_bounds__(512, 4)
void engram_kernel(const int*   __restrict__ tokens,
                   const float* __restrict__ tables,
                   float*       __restrict__ out) {
    const int bs = blockIdx.x;          // 0 .. B*S-1
    const int b  = bs >> 12;            // / 4096
    const int s  = bs & (S - 1);        // % 4096

    __shared__ unsigned hidx[PARTS];

    const int tid = threadIdx.x;
    if (tid < PARTS) {
        const int oi    = tid >> 2;     // 0 or 1
        const int head  = tid & 3;
        const int order = 2 + oi;
        const unsigned seed = 1337u + 97u * (unsigned)order + 17u * (unsigned)head;
        unsigned h = 0u;
        #pragma unroll 3
        for (int i = 0; i < order; i++) {
            const int pos = s - order + 1 + i;
            unsigned tok = 0u;
            if (pos >= 0) tok = (unsigned)tokens[b * S + pos];
            h = (h * PRIME + tok + seed) & (NUM_BUCKETS - 1);
        }
        hidx[tid] = h;
    }
    __syncthreads();

    // 512 threads each move one float4: 512*16B = 8KB = one output row.
    const int c    = tid;               // float4 index within the row
    const int part = c >> 6;            // 64 float4 per 256-float segment
    const int d4   = c & 63;

    const unsigned h = hidx[part];
    const float4* src = reinterpret_cast<const float4*>(
        tables + ((size_t)part * NUM_BUCKETS + h) * HEAD_DIM);
    float4 v = __ldg(src + d4);

    float4* dst = reinterpret_cast<float4*>(out + (size_t)bs * OUT_ROW);
    dst[c] = v;
}
} // namespace

extern "C" void kernel_launch(void* const* d_in, const int* in_sizes, int n_in,
                              void* d_out, int out_size) {
    // Resolve input order by element count: tokens = 16384, tables = 4194304.
    int ti = 0, wi = 1;
    if (n_in >= 2 && in_sizes[0] > in_sizes[1]) { ti = 1; wi = 0; }
    const int*   tokens = (const int*)d_in[ti];
    const float* tables = (const float*)d_in[wi];
    float*       out    = (float*)d_out;

    engram_kernel<<<B * S, 512>>>(tokens, tables, out);
}

// round 5
// speedup vs baseline: 1.7714x; 1.7714x over previous
#include <cuda_runtime.h>
#include <cuda_bf16.h>
#include <cstdint>

// EngramMemory: rolling-hash n-gram gather.
// tokens: (4, 4096) int32 -> d_in[tokens]
// tables: (8, 2048, 256) f32 -> d_in[tables]
// out:    (4, 4096, 2048) f32
//
// out[b][s][part*256 + d] = tables[part][h][d],  part = oi*4 + head
//   h = fold over the order-(2+oi) n-gram ending at s:
//       h = (h*1000003 + tok + seed) % 2048, seed = 1337 + 97*(2+oi) + 17*head
//   left zero-padded (pos < 0 -> token 0). All hash math fits in uint32.
//
// R4: 8 rows per CTA, 8-deep load burst per thread (MLP=8), streaming stores
// (__stcs) so the 128 MiB output stream doesn't evict the 16 MiB L2-resident
// table.

namespace {
constexpr int B = 4;
constexpr int S = 4096;
constexpr int NUM_BUCKETS = 2048;
constexpr int HEAD_DIM = 256;
constexpr int PARTS = 8;                   // 2 orders * 4 heads
constexpr int OUT_ROW4 = PARTS * HEAD_DIM / 4;  // 512 float4 per (b,s) row
constexpr int ROWS = 8;                    // output rows per CTA
constexpr unsigned PRIME = 1000003u;

__global__ __launch_bounds__(512, 2)
void engram_kernel(const int*   __restrict__ tokens,
                   const float* __restrict__ tables,
                   float*       __restrict__ out) {
    const int row0 = blockIdx.x * ROWS;     // base bs index
    const int tid  = threadIdx.x;

    __shared__ unsigned hidx[ROWS][PARTS];

    if (tid < ROWS * PARTS) {
        const int r    = tid >> 3;
        const int part = tid & 7;
        const int bs   = row0 + r;
        const int b    = bs >> 12;          // / 4096
        const int s    = bs & (S - 1);      // % 4096
        const int oi    = part >> 2;        // 0 or 1
        const int head  = part & 3;
        const int order = 2 + oi;
        const unsigned seed = 1337u + 97u * (unsigned)order + 17u * (unsigned)head;
        unsigned h = 0u;
        #pragma unroll 3
        for (int i = 0; i < order; i++) {
            const int pos = s - order + 1 + i;
            unsigned tok = 0u;
            if (pos >= 0) tok = (unsigned)tokens[b * S + pos];
            h = (h * PRIME + tok + seed) & (NUM_BUCKETS - 1);
        }
        hidx[r][part] = h;
    }
    __syncthreads();

    // Each thread moves one float4 per row, for 8 rows: 8 independent
    // LDG.128 in flight, then 8 STG.128.
    const int c    = tid;                   // float4 index within a row
    const int part = c >> 6;                // 64 float4 per 256-float head slice
    const int d4   = c & 63;

    const float4* __restrict__ tbl =
        reinterpret_cast<const float4*>(tables) +
        (size_t)part * (NUM_BUCKETS * HEAD_DIM / 4) + d4;
    float4* __restrict__ dst =
        reinterpret_cast<float4*>(out) + (size_t)row0 * OUT_ROW4 + c;

    float4 v[ROWS];
    #pragma unroll
    for (int r = 0; r < ROWS; r++) {
        v[r] = __ldg(tbl + (size_t)hidx[r][part] * (HEAD_DIM / 4));
    }
    #pragma unroll
    for (int r = 0; r < ROWS; r++) {
        __stcs(dst + r * OUT_ROW4, v[r]);
    }
}
} // namespace

extern "C" void kernel_launch(void* const* d_in, const int* in_sizes, int n_in,
                              void* d_out, int out_size) {
    // Resolve input order by element count: tokens = 16384, tables = 4194304.
    int ti = 0, wi = 1;
    if (n_in >= 2 && in_sizes[0] > in_sizes[1]) { ti = 1; wi = 0; }
    const int*   tokens = (const int*)d_in[ti];
    const float* tables = (const float*)d_in[wi];
    float*       out    = (float*)d_out;

    engram_kernel<<<(B * S) / ROWS, 512>>>(tokens, tables, out);
}